// round 11
// baseline (speedup 1.0000x reference)
#include <cuda_runtime.h>
#include <cuda_fp16.h>
#include <math.h>

typedef unsigned int u32;

// Problem constants
#define B_   8
#define S_   4096
#define D_   1024
#define M_   32
#define R_   (B_*S_)      // 32768 rows
#define NC_  64
#define CHUNK_ 64
#define KP_  1056         // K for k4: [X(1024) | Q(32)]
#define NS4  33           // 1056 / 32 K-chunks

// -------- device scratch --------
__device__ float  g_r [R_*M_];
__device__ float  g_w [R_*M_];
__device__ float  g_nm[R_*M_];
__device__ float  g_wqp[8*M_*D_];         // split-K partials for Wq
__device__ float  g_cvec[D_];
__device__ float  g_cvp[8*D_];            // split-K partials for cvec
__device__ float  g_cA[B_*NC_*M_];
__device__ float  g_cB[B_*NC_*M_];
__device__ float  g_ms[B_*NC_*M_];
__device__ __half g_xq[(size_t)R_*KP_];   // fp16 [X | Q]
__device__ __half g_wall[(size_t)KP_*D_]; // fp16 [Wo_x ; Wq], K-major rows of N=1024
__device__ __half g_wg[D_*96];            // fp16 packed [Wr|Ww|Wm]

// ---------------- helpers ----------------
__device__ __forceinline__ void mma_f16(float* c, const u32* a, const u32* b) {
    asm volatile(
        "mma.sync.aligned.m16n8k16.row.col.f32.f16.f16.f32 "
        "{%0,%1,%2,%3},{%4,%5,%6,%7},{%8,%9},{%0,%1,%2,%3};\n"
        : "+f"(c[0]), "+f"(c[1]), "+f"(c[2]), "+f"(c[3])
        : "r"(a[0]), "r"(a[1]), "r"(a[2]), "r"(a[3]), "r"(b[0]), "r"(b[1]));
}
__device__ __forceinline__ void ldsm_x4(u32* r, u32 addr) {
    asm volatile("ldmatrix.sync.aligned.m8n8.x4.shared.b16 {%0,%1,%2,%3},[%4];"
        : "=r"(r[0]), "=r"(r[1]), "=r"(r[2]), "=r"(r[3]) : "r"(addr));
}
__device__ __forceinline__ void ldsm_x2t(u32* r, u32 addr) {
    asm volatile("ldmatrix.sync.aligned.m8n8.x2.trans.shared.b16 {%0,%1},[%2];"
        : "=r"(r[0]), "=r"(r[1]) : "r"(addr));
}
__device__ __forceinline__ void ldsm_x4t(u32* r, u32 addr) {
    asm volatile("ldmatrix.sync.aligned.m8n8.x4.trans.shared.b16 {%0,%1,%2,%3},[%4];"
        : "=r"(r[0]), "=r"(r[1]), "=r"(r[2]), "=r"(r[3]) : "r"(addr));
}
__device__ __forceinline__ void cpa16(u32 saddr, const void* gptr) {
    asm volatile("cp.async.cg.shared.global [%0], [%1], 16;" :: "r"(saddr), "l"(gptr));
}
__device__ __forceinline__ void cpa_commit() { asm volatile("cp.async.commit_group;"); }
__device__ __forceinline__ void cpa_wait1()  { asm volatile("cp.async.wait_group 1;"); }
__device__ __forceinline__ void cpa_wait0()  { asm volatile("cp.async.wait_group 0;"); }

// ============================================================
// K0: fused pack kernel (X->fp16, Wo_x->g_wall, gate weights)
// grid: [0,32768) X | [32768,33792) Wo | [33792,34176) gates
// ============================================================
__global__ void __launch_bounds__(256) k0_pack(
    const float* __restrict__ x, const float* __restrict__ Wo,
    const float* __restrict__ Wr, const float* __restrict__ Ww,
    const float* __restrict__ Wm)
{
    int bid = blockIdx.x;
    if (bid < 32768) {
        int idx = bid * 256 + threadIdx.x;     // one float4 of X
        int r = idx >> 8;
        int c4 = idx & 255;
        float4 v = *reinterpret_cast<const float4*>(x + (size_t)idx * 4);
        __half2 h0 = __floats2half2_rn(v.x, v.y);
        __half2 h1 = __floats2half2_rn(v.z, v.w);
        __half* dst = g_xq + (size_t)r * KP_ + c4 * 4;
        *reinterpret_cast<__half2*>(dst)     = h0;
        *reinterpret_cast<__half2*>(dst + 2) = h1;
    } else if (bid < 33792) {
        int i = (bid - 32768) * 256 + threadIdx.x;   // float4 over D_*D_
        float4 v = *reinterpret_cast<const float4*>(Wo + (size_t)i * 4);
        __half2 h0 = __floats2half2_rn(v.x, v.y);
        __half2 h1 = __floats2half2_rn(v.z, v.w);
        *reinterpret_cast<__half2*>(g_wall + (size_t)i * 4)     = h0;
        *reinterpret_cast<__half2*>(g_wall + (size_t)i * 4 + 2) = h1;
    } else {
        int i = (bid - 33792) * 256 + threadIdx.x;   // over D_*96
        int row = i / 96;
        int n = i % 96;
        float v;
        if (n < 32)      v = Wr[row * M_ + n];
        else if (n < 64) v = Ww[row * M_ + (n - 32)];
        else             v = Wm[row * M_ + (n - 64)];
        g_wg[i] = __float2half_rn(v);
    }
}

// ============================================================
// K1: gates GEMM (32768 x 96) = X @ [Wr|Ww|Wm], mma.sync fp16
// ============================================================
#define APADH   40
#define A_BYT   10240
#define B1PADH  104
#define STG1    16896

__device__ __forceinline__ void k1_copy(u32 sbase, int rowBase, int t, int k0)
{
#pragma unroll
    for (int u = 0; u < 2; u++) {
        int idx = t + u * 256;
        int row = idx >> 2;
        int c = idx & 3;
        const __half* g = g_xq + (size_t)(rowBase + row) * KP_ + k0 + c * 8;
        cpa16(sbase + row * 80 + c * 16, g);
    }
#pragma unroll
    for (int u = 0; u < 2; u++) {
        int idx = t + u * 256;
        if (idx < 384) {
            int row = idx / 12;
            int c = idx % 12;
            const __half* g = g_wg + (size_t)(k0 + row) * 96 + c * 8;
            cpa16(sbase + A_BYT + row * 208 + c * 16, g);
        }
    }
}

__global__ void __launch_bounds__(256) k1_rwm(
    const float* __restrict__ br, const float* __restrict__ bw,
    const float* __restrict__ bm)
{
    __shared__ __align__(16) char sm1[2 * STG1];
    const int t = threadIdx.x;
    const int rowBase = blockIdx.x * 128;
    const int wid = t >> 5;
    const int lane = t & 31;
    const int wm = wid >> 1;
    const int wn = wid & 1;
    const u32 smBase = (u32)__cvta_generic_to_shared(sm1);

    float acc[2][6][4];
#pragma unroll
    for (int i = 0; i < 2; i++) {
#pragma unroll
        for (int j = 0; j < 6; j++) {
#pragma unroll
            for (int kq = 0; kq < 4; kq++) acc[i][j][kq] = 0.f;
        }
    }

    const int NS = 32;
    k1_copy(smBase, rowBase, t, 0);
    cpa_commit();
    k1_copy(smBase + STG1, rowBase, t, 32);
    cpa_commit();
    cpa_wait1();
    __syncthreads();

    for (int s = 0; s < NS; s++) {
        u32 buf = smBase + (u32)(s & 1) * STG1;
#pragma unroll
        for (int kh = 0; kh < 2; kh++) {
            int kk = kh * 16;
            u32 a[2][4];
#pragma unroll
            for (int mt = 0; mt < 2; mt++) {
                int r = wm * 32 + mt * 16 + (lane & 15);
                int kc = kk + ((lane >> 4) << 3);
                ldsm_x4(a[mt], buf + (r * APADH + kc) * 2);
            }
            int krow = kk + (lane & 7) + ((lane >> 3) & 1) * 8;
#pragma unroll
            for (int nt = 0; nt < 6; nt++) {
                int nn = wn * 48 + nt * 8;
                u32 b[2];
                ldsm_x2t(b, buf + A_BYT + (krow * B1PADH + nn) * 2);
#pragma unroll
                for (int mt = 0; mt < 2; mt++) {
                    mma_f16(acc[mt][nt], a[mt], b);
                }
            }
        }
        __syncthreads();
        if (s + 2 < NS) {
            k1_copy(buf, rowBase, t, (s + 2) * 32);
            cpa_commit();
        }
        if (s + 1 < NS) {
            if (s + 2 < NS) cpa_wait1();
            else cpa_wait0();
            __syncthreads();
        }
    }

#pragma unroll
    for (int mt = 0; mt < 2; mt++) {
#pragma unroll
        for (int nt = 0; nt < 6; nt++) {
            int n = wn * 48 + nt * 8 + (lane & 3) * 2;
            int row0 = rowBase + wm * 32 + mt * 16 + (lane >> 2);
#pragma unroll
            for (int half = 0; half < 2; half++) {
                int row = row0 + half * 8;
                float v0 = acc[mt][nt][half * 2 + 0];
                float v1 = acc[mt][nt][half * 2 + 1];
                float2 o;
                if (n < 32) {
                    o.x = 1.f / (1.f + expf(-(v0 + br[n])));
                    o.y = 1.f / (1.f + expf(-(v1 + br[n + 1])));
                    *reinterpret_cast<float2*>(&g_r[(size_t)row * M_ + n]) = o;
                } else if (n < 64) {
                    o.x = 1.f / (1.f + expf(-(v0 + bw[n - 32])));
                    o.y = 1.f / (1.f + expf(-(v1 + bw[n - 31])));
                    *reinterpret_cast<float2*>(&g_w[(size_t)row * M_ + n - 32]) = o;
                } else {
                    o.x = v0 + bm[n - 64];
                    o.y = v1 + bm[n - 63];
                    *reinterpret_cast<float2*>(&g_nm[(size_t)row * M_ + n - 64]) = o;
                }
            }
        }
    }
}

// ============================================================
// K2: Wq = Wp @ Wo_m and cvec = bp @ Wo_m + bo, split-K x8
// part kernel: grid 96 = 64 (wq: e8 x k8) + 32 (cvec: e4 x k8)
// ============================================================
__global__ void __launch_bounds__(256) k2_part(
    const float* __restrict__ Wp, const float* __restrict__ Wo,
    const float* __restrict__ bp)
{
    __shared__ float Ps[32][128];
    const int t = threadIdx.x;
    int bid = blockIdx.x;
    if (bid < 64) {
        int eb = bid & 7;
        int ks = bid >> 3;
        const int e = eb * 128 + (t & 127);
        const int d0 = ks * 128;
        const int mg = t >> 7;
        float acc[16];
#pragma unroll
        for (int i = 0; i < 16; i++) acc[i] = 0.f;
#pragma unroll
        for (int u = 0; u < 16; u++) {
            int idx = t + u * 256;
            Ps[idx >> 7][idx & 127] = Wp[(idx >> 7) * D_ + d0 + (idx & 127)];
        }
        __syncthreads();
#pragma unroll 4
        for (int dd = 0; dd < 128; dd++) {
            float wo = Wo[(size_t)(D_ + d0 + dd) * D_ + e];
#pragma unroll
            for (int i = 0; i < 16; i++)
                acc[i] += Ps[mg * 16 + i][dd] * wo;
        }
#pragma unroll
        for (int i = 0; i < 16; i++)
            g_wqp[((size_t)ks * M_ + mg * 16 + i) * D_ + e] = acc[i];
    } else {
        int b2 = bid - 64;
        int eb = b2 & 3;
        int ks = b2 >> 2;
        int e = eb * 256 + t;
        int d0 = ks * 128;
        float acc = 0.f;
#pragma unroll 4
        for (int dd = 0; dd < 128; dd++)
            acc += bp[d0 + dd] * Wo[(size_t)(D_ + d0 + dd) * D_ + e];
        g_cvp[ks * D_ + e] = acc;
    }
}

// red kernel: grid 132 = 128 (wq reduce -> fp16 g_wall rows 1024+) + 4 (cvec)
__global__ void __launch_bounds__(256) k2_red(const float* __restrict__ bo)
{
    int bid = blockIdx.x;
    if (bid < 128) {
        int i = bid * 256 + threadIdx.x;   // over M_*D_
        float s = 0.f;
#pragma unroll
        for (int ks = 0; ks < 8; ks++)
            s += g_wqp[ks * M_ * D_ + i];
        g_wall[(size_t)1024 * D_ + i] = __float2half_rn(s);
    } else {
        int e = (bid - 128) * 256 + threadIdx.x;
        float s = bo[e];
#pragma unroll
        for (int ks = 0; ks < 8; ks++)
            s += g_cvp[ks * D_ + e];
        g_cvec[e] = s;
    }
}

// ============================================================
// K3: chunked parallel scan of mem[t+1] = (1-w)*mem + w*nm
// ============================================================
__global__ void __launch_bounds__(256) k3a_chunk()
{
    int g = blockIdx.x * 256 + threadIdx.x;
    int m = g & 31;
    int c = (g >> 5) & (NC_ - 1);
    int b = g >> 11;
    size_t base = ((size_t)b * S_ + (size_t)c * CHUNK_) * M_ + m;
    float A = 1.f;
    float Bc = 0.f;
    for (int i = 0; i < CHUNK_; i++) {
        size_t idx = base + (size_t)i * M_;
        float wv = g_w[idx];
        float a = 1.f - wv;
        A = a * A;
        Bc = a * Bc + wv * g_nm[idx];
    }
    g_cA[g] = A;
    g_cB[g] = Bc;
}

__global__ void k3b_prefix()
{
    int t = threadIdx.x;
    int b = t >> 5;
    int m = t & 31;
    float mem = 0.f;
    for (int g0 = 0; g0 < NC_; g0 += 16) {
        float av[16];
        float bv[16];
#pragma unroll
        for (int j = 0; j < 16; j++) {
            int gi = (b * NC_ + g0 + j) * 32 + m;
            av[j] = g_cA[gi];
            bv[j] = g_cB[gi];
        }
#pragma unroll
        for (int j = 0; j < 16; j++) {
            int gi = (b * NC_ + g0 + j) * 32 + m;
            g_ms[gi] = mem;
            mem = av[j] * mem + bv[j];
        }
    }
}

__global__ void __launch_bounds__(256) k3c_emit()
{
    int g = blockIdx.x * 256 + threadIdx.x;
    int m = g & 31;
    int c = (g >> 5) & (NC_ - 1);
    int b = g >> 11;
    int row0 = b * S_ + c * CHUNK_;
    float mem = g_ms[g];
    for (int i = 0; i < CHUNK_; i++) {
        int row = row0 + i;
        size_t idx = (size_t)row * M_ + m;
        float rv = g_r[idx];
        float wv = g_w[idx];
        float nv = g_nm[idx];
        g_xq[(size_t)row * KP_ + 1024 + m] = __float2half_rn(rv * mem);
        mem = (1.f - wv) * mem + wv * nv;
    }
}

// ============================================================
// K4: out(32768,1024) = tanh( g_xq @ g_wall + cvec ), K=1056
// CTA 128x128, 128 threads (4 warps, 2m x 2n), warp tile 64x64
// 3-stage cp.async ring, ONE barrier per chunk, natural occupancy
// ============================================================
#define B4PADH  136
#define B4_BYT  8704
#define STG4    18944              // A_BYT + B4_BYT per stage
#define K4_DYN  (3 * STG4)        // 56832 B dynamic smem

__device__ __forceinline__ void k4_copy(u32 sbase, int rowBase, int e0, int t, int k0)
{
#pragma unroll
    for (int u = 0; u < 4; u++) {
        int idx = t + u * 128;
        int row = idx >> 2;
        int c = idx & 3;
        cpa16(sbase + row * 80 + c * 16,
              g_xq + (size_t)(rowBase + row) * KP_ + k0 + c * 8);
    }
#pragma unroll
    for (int u = 0; u < 4; u++) {
        int idx = t + u * 128;
        int row = idx >> 4;
        int c = idx & 15;
        cpa16(sbase + A_BYT + row * 272 + c * 16,
              g_wall + (size_t)(k0 + row) * D_ + e0 + c * 8);
    }
}

__global__ void __launch_bounds__(128) k4_mm(float* __restrict__ out)
{
    extern __shared__ __align__(16) char sm4[];
    const int t = threadIdx.x;
    const int rowBase = blockIdx.y * 128;
    const int e0 = blockIdx.x * 128;
    const int wid = t >> 5;
    const int lane = t & 31;
    const int wm = wid >> 1;     // 0..1 -> rows wm*64
    const int wn = wid & 1;      // 0..1 -> cols wn*64
    const u32 smBase = (u32)__cvta_generic_to_shared(sm4);

    float acc[4][8][4];
#pragma unroll
    for (int i = 0; i < 4; i++) {
#pragma unroll
        for (int j = 0; j < 8; j++) {
#pragma unroll
            for (int kq = 0; kq < 4; kq++) acc[i][j][kq] = 0.f;
        }
    }

    // preload stages 0,1
    k4_copy(smBase, rowBase, e0, t, 0);
    cpa_commit();
    k4_copy(smBase + STG4, rowBase, e0, t, 32);
    cpa_commit();
    cpa_wait1();                 // stage 0 landed
    __syncthreads();

    int cur = 0;
    for (int s = 0; s < NS4; s++) {
        // issue copy of chunk s+2 into stage (cur+2)%3 BEFORE the MMAs
        if (s + 2 < NS4) {
            int pre = cur + 2;
            if (pre >= 3) pre -= 3;
            k4_copy(smBase + (u32)pre * STG4, rowBase, e0, t, (s + 2) * 32);
            cpa_commit();
        }
        u32 buf = smBase + (u32)cur * STG4;
#pragma unroll
        for (int kh = 0; kh < 2; kh++) {
            int kk = kh * 16;
            u32 a[4][4];
#pragma unroll
            for (int mt = 0; mt < 4; mt++) {
                int r = wm * 64 + mt * 16 + (lane & 15);
                int kc = kk + ((lane >> 4) << 3);
                ldsm_x4(a[mt], buf + (r * APADH + kc) * 2);
            }
            int krow = kk + (lane & 7) + ((lane >> 3) & 1) * 8;
            int ncol = ((lane >> 4) << 3);
#pragma unroll
            for (int nt4 = 0; nt4 < 4; nt4++) {
                int nn = wn * 64 + nt4 * 16;
                u32 b[4];
                ldsm_x4t(b, buf + A_BYT + (krow * B4PADH + nn + ncol) * 2);
#pragma unroll
                for (int mt = 0; mt < 4; mt++) {
                    mma_f16(acc[mt][2 * nt4],     a[mt], b);
                    mma_f16(acc[mt][2 * nt4 + 1], a[mt], b + 2);
                }
            }
        }
        // chunk s+1 must have landed before next iteration reads it
        if (s + 2 < NS4)      cpa_wait1();
        else if (s + 1 < NS4) cpa_wait0();
        __syncthreads();         // single barrier per chunk
        cur = (cur == 2) ? 0 : cur + 1;
    }

    // epilogue: + cvec, tanh
#pragma unroll
    for (int mt = 0; mt < 4; mt++) {
#pragma unroll
        for (int nt = 0; nt < 8; nt++) {
            int col = e0 + wn * 64 + nt * 8 + (lane & 3) * 2;
            float cv0 = g_cvec[col];
            float cv1 = g_cvec[col + 1];
            int row0 = rowBase + wm * 64 + mt * 16 + (lane >> 2);
#pragma unroll
            for (int half = 0; half < 2; half++) {
                int row = row0 + half * 8;
                float2 o;
                o.x = tanhf(acc[mt][nt][half * 2 + 0] + cv0);
                o.y = tanhf(acc[mt][nt][half * 2 + 1] + cv1);
                *reinterpret_cast<float2*>(&out[(size_t)row * D_ + col]) = o;
            }
        }
    }
}

// ============================================================
// launch
// ============================================================
extern "C" void kernel_launch(void* const* d_in, const int* in_sizes, int n_in,
                              void* d_out, int out_size)
{
    const float* x  = (const float*)d_in[0];
    const float* Wr = (const float*)d_in[1];
    const float* br = (const float*)d_in[2];
    const float* Ww = (const float*)d_in[3];
    const float* bw = (const float*)d_in[4];
    const float* Wm = (const float*)d_in[5];
    const float* bm = (const float*)d_in[6];
    const float* Wp = (const float*)d_in[7];
    const float* bp = (const float*)d_in[8];
    const float* Wo = (const float*)d_in[9];
    const float* bo = (const float*)d_in[10];
    float* out = (float*)d_out;

    cudaFuncSetAttribute(k4_mm, cudaFuncAttributeMaxDynamicSharedMemorySize, K4_DYN);

    // 0) fused pack: X->fp16, Wo_x->g_wall, gate weights
    k0_pack<<<34176, 256>>>(x, Wo, Wr, Ww, Wm);

    // 1) gates GEMM (mma.sync fp16)
    k1_rwm<<<R_ / 128, 256>>>(br, bw, bm);

    // 2) folded weights (split-K, fused part + fused reduce/convert)
    k2_part<<<96, 256>>>(Wp, Wo, bp);
    k2_red<<<132, 256>>>(bo);

    // 3) linear-recurrence scan (emits fp16 Q into g_xq)
    k3a_chunk<<<(B_ * M_ * NC_) / 256, 256>>>();
    k3b_prefix<<<1, 256>>>();
    k3c_emit<<<(B_ * M_ * NC_) / 256, 256>>>();

    // 4) output GEMM + tanh (mma.sync fp16, 3-stage ring, 1 barrier/chunk)
    dim3 grid4(D_ / 128, R_ / 128);
    k4_mm<<<grid4, 128, K4_DYN>>>(out);
}

// round 12
// speedup vs baseline: 1.4506x; 1.4506x over previous
#include <cuda_runtime.h>
#include <cuda_fp16.h>
#include <math.h>

typedef unsigned int u32;

// Problem constants
#define B_   8
#define S_   4096
#define D_   1024
#define M_   32
#define R_   (B_*S_)      // 32768 rows
#define NC_  64
#define CHUNK_ 64
#define KP_  1056         // K for k4: [X(1024) | Q(32)]
#define NS4  33           // 1056 / 32 K-chunks

// -------- device scratch --------
__device__ float  g_r [R_*M_];
__device__ float  g_w [R_*M_];
__device__ float  g_nm[R_*M_];
__device__ float  g_wqp[8*M_*D_];         // split-K partials for Wq
__device__ float  g_cvec[D_];
__device__ float  g_cvp[8*D_];            // split-K partials for cvec
__device__ float  g_cA[B_*NC_*M_];
__device__ float  g_cB[B_*NC_*M_];
__device__ float  g_ms[B_*NC_*M_];
__device__ __half g_xq[(size_t)R_*KP_];   // fp16 [X | Q]
__device__ __half g_wall[(size_t)KP_*D_]; // fp16 [Wo_x ; Wq], K-major rows of N=1024
__device__ __half g_wg[D_*96];            // fp16 packed [Wr|Ww|Wm]

// ---------------- helpers ----------------
__device__ __forceinline__ void mma_f16(float* c, const u32* a, const u32* b) {
    asm volatile(
        "mma.sync.aligned.m16n8k16.row.col.f32.f16.f16.f32 "
        "{%0,%1,%2,%3},{%4,%5,%6,%7},{%8,%9},{%0,%1,%2,%3};\n"
        : "+f"(c[0]), "+f"(c[1]), "+f"(c[2]), "+f"(c[3])
        : "r"(a[0]), "r"(a[1]), "r"(a[2]), "r"(a[3]), "r"(b[0]), "r"(b[1]));
}
__device__ __forceinline__ void ldsm_x4(u32* r, u32 addr) {
    asm volatile("ldmatrix.sync.aligned.m8n8.x4.shared.b16 {%0,%1,%2,%3},[%4];"
        : "=r"(r[0]), "=r"(r[1]), "=r"(r[2]), "=r"(r[3]) : "r"(addr));
}
__device__ __forceinline__ void ldsm_x2t(u32* r, u32 addr) {
    asm volatile("ldmatrix.sync.aligned.m8n8.x2.trans.shared.b16 {%0,%1},[%2];"
        : "=r"(r[0]), "=r"(r[1]) : "r"(addr));
}
__device__ __forceinline__ void ldsm_x4t(u32* r, u32 addr) {
    asm volatile("ldmatrix.sync.aligned.m8n8.x4.trans.shared.b16 {%0,%1,%2,%3},[%4];"
        : "=r"(r[0]), "=r"(r[1]), "=r"(r[2]), "=r"(r[3]) : "r"(addr));
}
__device__ __forceinline__ void cpa16(u32 saddr, const void* gptr) {
    asm volatile("cp.async.cg.shared.global [%0], [%1], 16;" :: "r"(saddr), "l"(gptr));
}
__device__ __forceinline__ void cpa_commit() { asm volatile("cp.async.commit_group;"); }
__device__ __forceinline__ void cpa_wait1()  { asm volatile("cp.async.wait_group 1;"); }
__device__ __forceinline__ void cpa_wait0()  { asm volatile("cp.async.wait_group 0;"); }

// ============================================================
// K0: fused pack kernel (X->fp16, Wo_x->g_wall, gate weights)
// grid: [0,32768) X | [32768,33792) Wo | [33792,34176) gates
// ============================================================
__global__ void __launch_bounds__(256) k0_pack(
    const float* __restrict__ x, const float* __restrict__ Wo,
    const float* __restrict__ Wr, const float* __restrict__ Ww,
    const float* __restrict__ Wm)
{
    int bid = blockIdx.x;
    if (bid < 32768) {
        int idx = bid * 256 + threadIdx.x;     // one float4 of X
        int r = idx >> 8;
        int c4 = idx & 255;
        float4 v = *reinterpret_cast<const float4*>(x + (size_t)idx * 4);
        __half2 h0 = __floats2half2_rn(v.x, v.y);
        __half2 h1 = __floats2half2_rn(v.z, v.w);
        __half* dst = g_xq + (size_t)r * KP_ + c4 * 4;
        *reinterpret_cast<__half2*>(dst)     = h0;
        *reinterpret_cast<__half2*>(dst + 2) = h1;
    } else if (bid < 33792) {
        int i = (bid - 32768) * 256 + threadIdx.x;   // float4 over D_*D_
        float4 v = *reinterpret_cast<const float4*>(Wo + (size_t)i * 4);
        __half2 h0 = __floats2half2_rn(v.x, v.y);
        __half2 h1 = __floats2half2_rn(v.z, v.w);
        *reinterpret_cast<__half2*>(g_wall + (size_t)i * 4)     = h0;
        *reinterpret_cast<__half2*>(g_wall + (size_t)i * 4 + 2) = h1;
    } else {
        int i = (bid - 33792) * 256 + threadIdx.x;   // over D_*96
        int row = i / 96;
        int n = i % 96;
        float v;
        if (n < 32)      v = Wr[row * M_ + n];
        else if (n < 64) v = Ww[row * M_ + (n - 32)];
        else             v = Wm[row * M_ + (n - 64)];
        g_wg[i] = __float2half_rn(v);
    }
}

// ============================================================
// K1: gates GEMM (32768 x 96) = X @ [Wr|Ww|Wm], mma.sync fp16
// ============================================================
#define APADH   40
#define A_BYT   10240
#define B1PADH  104
#define STG1    16896

__device__ __forceinline__ void k1_copy(u32 sbase, int rowBase, int t, int k0)
{
#pragma unroll
    for (int u = 0; u < 2; u++) {
        int idx = t + u * 256;
        int row = idx >> 2;
        int c = idx & 3;
        const __half* g = g_xq + (size_t)(rowBase + row) * KP_ + k0 + c * 8;
        cpa16(sbase + row * 80 + c * 16, g);
    }
#pragma unroll
    for (int u = 0; u < 2; u++) {
        int idx = t + u * 256;
        if (idx < 384) {
            int row = idx / 12;
            int c = idx % 12;
            const __half* g = g_wg + (size_t)(k0 + row) * 96 + c * 8;
            cpa16(sbase + A_BYT + row * 208 + c * 16, g);
        }
    }
}

__global__ void __launch_bounds__(256) k1_rwm(
    const float* __restrict__ br, const float* __restrict__ bw,
    const float* __restrict__ bm)
{
    __shared__ __align__(16) char sm1[2 * STG1];
    const int t = threadIdx.x;
    const int rowBase = blockIdx.x * 128;
    const int wid = t >> 5;
    const int lane = t & 31;
    const int wm = wid >> 1;
    const int wn = wid & 1;
    const u32 smBase = (u32)__cvta_generic_to_shared(sm1);

    float acc[2][6][4];
#pragma unroll
    for (int i = 0; i < 2; i++) {
#pragma unroll
        for (int j = 0; j < 6; j++) {
#pragma unroll
            for (int kq = 0; kq < 4; kq++) acc[i][j][kq] = 0.f;
        }
    }

    const int NS = 32;
    k1_copy(smBase, rowBase, t, 0);
    cpa_commit();
    k1_copy(smBase + STG1, rowBase, t, 32);
    cpa_commit();
    cpa_wait1();
    __syncthreads();

    for (int s = 0; s < NS; s++) {
        u32 buf = smBase + (u32)(s & 1) * STG1;
#pragma unroll
        for (int kh = 0; kh < 2; kh++) {
            int kk = kh * 16;
            u32 a[2][4];
#pragma unroll
            for (int mt = 0; mt < 2; mt++) {
                int r = wm * 32 + mt * 16 + (lane & 15);
                int kc = kk + ((lane >> 4) << 3);
                ldsm_x4(a[mt], buf + (r * APADH + kc) * 2);
            }
            int krow = kk + (lane & 7) + ((lane >> 3) & 1) * 8;
#pragma unroll
            for (int nt = 0; nt < 6; nt++) {
                int nn = wn * 48 + nt * 8;
                u32 b[2];
                ldsm_x2t(b, buf + A_BYT + (krow * B1PADH + nn) * 2);
#pragma unroll
                for (int mt = 0; mt < 2; mt++) {
                    mma_f16(acc[mt][nt], a[mt], b);
                }
            }
        }
        __syncthreads();
        if (s + 2 < NS) {
            k1_copy(buf, rowBase, t, (s + 2) * 32);
            cpa_commit();
        }
        if (s + 1 < NS) {
            if (s + 2 < NS) cpa_wait1();
            else cpa_wait0();
            __syncthreads();
        }
    }

#pragma unroll
    for (int mt = 0; mt < 2; mt++) {
#pragma unroll
        for (int nt = 0; nt < 6; nt++) {
            int n = wn * 48 + nt * 8 + (lane & 3) * 2;
            int row0 = rowBase + wm * 32 + mt * 16 + (lane >> 2);
#pragma unroll
            for (int half = 0; half < 2; half++) {
                int row = row0 + half * 8;
                float v0 = acc[mt][nt][half * 2 + 0];
                float v1 = acc[mt][nt][half * 2 + 1];
                float2 o;
                if (n < 32) {
                    o.x = 1.f / (1.f + expf(-(v0 + br[n])));
                    o.y = 1.f / (1.f + expf(-(v1 + br[n + 1])));
                    *reinterpret_cast<float2*>(&g_r[(size_t)row * M_ + n]) = o;
                } else if (n < 64) {
                    o.x = 1.f / (1.f + expf(-(v0 + bw[n - 32])));
                    o.y = 1.f / (1.f + expf(-(v1 + bw[n - 31])));
                    *reinterpret_cast<float2*>(&g_w[(size_t)row * M_ + n - 32]) = o;
                } else {
                    o.x = v0 + bm[n - 64];
                    o.y = v1 + bm[n - 63];
                    *reinterpret_cast<float2*>(&g_nm[(size_t)row * M_ + n - 64]) = o;
                }
            }
        }
    }
}

// ============================================================
// K2: Wq = Wp @ Wo_m and cvec = bp @ Wo_m + bo, split-K x8
// part kernel: grid 96 = 64 (wq: e8 x k8) + 32 (cvec: e4 x k8)
// ============================================================
__global__ void __launch_bounds__(256) k2_part(
    const float* __restrict__ Wp, const float* __restrict__ Wo,
    const float* __restrict__ bp)
{
    __shared__ float Ps[32][128];
    const int t = threadIdx.x;
    int bid = blockIdx.x;
    if (bid < 64) {
        int eb = bid & 7;
        int ks = bid >> 3;
        const int e = eb * 128 + (t & 127);
        const int d0 = ks * 128;
        const int mg = t >> 7;
        float acc[16];
#pragma unroll
        for (int i = 0; i < 16; i++) acc[i] = 0.f;
#pragma unroll
        for (int u = 0; u < 16; u++) {
            int idx = t + u * 256;
            Ps[idx >> 7][idx & 127] = Wp[(idx >> 7) * D_ + d0 + (idx & 127)];
        }
        __syncthreads();
#pragma unroll 4
        for (int dd = 0; dd < 128; dd++) {
            float wo = Wo[(size_t)(D_ + d0 + dd) * D_ + e];
#pragma unroll
            for (int i = 0; i < 16; i++)
                acc[i] += Ps[mg * 16 + i][dd] * wo;
        }
#pragma unroll
        for (int i = 0; i < 16; i++)
            g_wqp[((size_t)ks * M_ + mg * 16 + i) * D_ + e] = acc[i];
    } else {
        int b2 = bid - 64;
        int eb = b2 & 3;
        int ks = b2 >> 2;
        int e = eb * 256 + t;
        int d0 = ks * 128;
        float acc = 0.f;
#pragma unroll 4
        for (int dd = 0; dd < 128; dd++)
            acc += bp[d0 + dd] * Wo[(size_t)(D_ + d0 + dd) * D_ + e];
        g_cvp[ks * D_ + e] = acc;
    }
}

// red kernel: grid 132 = 128 (wq reduce -> fp16 g_wall rows 1024+) + 4 (cvec)
__global__ void __launch_bounds__(256) k2_red(const float* __restrict__ bo)
{
    int bid = blockIdx.x;
    if (bid < 128) {
        int i = bid * 256 + threadIdx.x;   // over M_*D_
        float s = 0.f;
#pragma unroll
        for (int ks = 0; ks < 8; ks++)
            s += g_wqp[ks * M_ * D_ + i];
        g_wall[(size_t)1024 * D_ + i] = __float2half_rn(s);
    } else {
        int e = (bid - 128) * 256 + threadIdx.x;
        float s = bo[e];
#pragma unroll
        for (int ks = 0; ks < 8; ks++)
            s += g_cvp[ks * D_ + e];
        g_cvec[e] = s;
    }
}

// ============================================================
// K3: chunked parallel scan of mem[t+1] = (1-w)*mem + w*nm
// ============================================================
__global__ void __launch_bounds__(256) k3a_chunk()
{
    int g = blockIdx.x * 256 + threadIdx.x;
    int m = g & 31;
    int c = (g >> 5) & (NC_ - 1);
    int b = g >> 11;
    size_t base = ((size_t)b * S_ + (size_t)c * CHUNK_) * M_ + m;
    float A = 1.f;
    float Bc = 0.f;
    for (int i = 0; i < CHUNK_; i++) {
        size_t idx = base + (size_t)i * M_;
        float wv = g_w[idx];
        float a = 1.f - wv;
        A = a * A;
        Bc = a * Bc + wv * g_nm[idx];
    }
    g_cA[g] = A;
    g_cB[g] = Bc;
}

__global__ void k3b_prefix()
{
    int t = threadIdx.x;
    int b = t >> 5;
    int m = t & 31;
    float mem = 0.f;
    for (int g0 = 0; g0 < NC_; g0 += 16) {
        float av[16];
        float bv[16];
#pragma unroll
        for (int j = 0; j < 16; j++) {
            int gi = (b * NC_ + g0 + j) * 32 + m;
            av[j] = g_cA[gi];
            bv[j] = g_cB[gi];
        }
#pragma unroll
        for (int j = 0; j < 16; j++) {
            int gi = (b * NC_ + g0 + j) * 32 + m;
            g_ms[gi] = mem;
            mem = av[j] * mem + bv[j];
        }
    }
}

__global__ void __launch_bounds__(256) k3c_emit()
{
    int g = blockIdx.x * 256 + threadIdx.x;
    int m = g & 31;
    int c = (g >> 5) & (NC_ - 1);
    int b = g >> 11;
    int row0 = b * S_ + c * CHUNK_;
    float mem = g_ms[g];
    for (int i = 0; i < CHUNK_; i++) {
        int row = row0 + i;
        size_t idx = (size_t)row * M_ + m;
        float rv = g_r[idx];
        float wv = g_w[idx];
        float nv = g_nm[idx];
        g_xq[(size_t)row * KP_ + 1024 + m] = __float2half_rn(rv * mem);
        mem = (1.f - wv) * mem + wv * nv;
    }
}

// ============================================================
// K4: out(32768,1024) = tanh( g_xq @ g_wall + cvec ), K=1056
// CTA 128x128, 128 threads (4 warps, 2m x 2n), warp tile 64x64
// R10-exact: static smem, 2-stage, copy AFTER MMA, two barriers
// ============================================================
#define B4PADH  136
#define B4_BYT  8704
#define STG4    18944      // A_BYT + B4_BYT

__device__ __forceinline__ void k4_copy(u32 sbase, int rowBase, int e0, int t, int k0)
{
#pragma unroll
    for (int u = 0; u < 4; u++) {
        int idx = t + u * 128;
        int row = idx >> 2;
        int c = idx & 3;
        cpa16(sbase + row * 80 + c * 16,
              g_xq + (size_t)(rowBase + row) * KP_ + k0 + c * 8);
    }
#pragma unroll
    for (int u = 0; u < 4; u++) {
        int idx = t + u * 128;
        int row = idx >> 4;
        int c = idx & 15;
        cpa16(sbase + A_BYT + row * 272 + c * 16,
              g_wall + (size_t)(k0 + row) * D_ + e0 + c * 8);
    }
}

__global__ void __launch_bounds__(128) k4_mm(float* __restrict__ out)
{
    __shared__ __align__(16) char sm4[2 * STG4];
    const int t = threadIdx.x;
    const int rowBase = blockIdx.y * 128;
    const int e0 = blockIdx.x * 128;
    const int wid = t >> 5;
    const int lane = t & 31;
    const int wm = wid >> 1;     // 0..1 -> rows wm*64
    const int wn = wid & 1;      // 0..1 -> cols wn*64
    const u32 smBase = (u32)__cvta_generic_to_shared(sm4);

    float acc[4][8][4];
#pragma unroll
    for (int i = 0; i < 4; i++) {
#pragma unroll
        for (int j = 0; j < 8; j++) {
#pragma unroll
            for (int kq = 0; kq < 4; kq++) acc[i][j][kq] = 0.f;
        }
    }

    k4_copy(smBase, rowBase, e0, t, 0);
    cpa_commit();
    k4_copy(smBase + STG4, rowBase, e0, t, 32);
    cpa_commit();
    cpa_wait1();
    __syncthreads();

    for (int s = 0; s < NS4; s++) {
        u32 buf = smBase + (u32)(s & 1) * STG4;
#pragma unroll
        for (int kh = 0; kh < 2; kh++) {
            int kk = kh * 16;
            u32 a[4][4];
#pragma unroll
            for (int mt = 0; mt < 4; mt++) {
                int r = wm * 64 + mt * 16 + (lane & 15);
                int kc = kk + ((lane >> 4) << 3);
                ldsm_x4(a[mt], buf + (r * APADH + kc) * 2);
            }
            int krow = kk + (lane & 7) + ((lane >> 3) & 1) * 8;
            int ncol = ((lane >> 4) << 3);
#pragma unroll
            for (int nt4 = 0; nt4 < 4; nt4++) {
                int nn = wn * 64 + nt4 * 16;
                u32 b[4];
                ldsm_x4t(b, buf + A_BYT + (krow * B4PADH + nn + ncol) * 2);
#pragma unroll
                for (int mt = 0; mt < 4; mt++) {
                    mma_f16(acc[mt][2 * nt4],     a[mt], b);
                    mma_f16(acc[mt][2 * nt4 + 1], a[mt], b + 2);
                }
            }
        }
        __syncthreads();
        if (s + 2 < NS4) {
            k4_copy(buf, rowBase, e0, t, (s + 2) * 32);
            cpa_commit();
        }
        if (s + 1 < NS4) {
            if (s + 2 < NS4) cpa_wait1();
            else cpa_wait0();
            __syncthreads();
        }
    }

    // epilogue: + cvec, tanh
#pragma unroll
    for (int mt = 0; mt < 4; mt++) {
#pragma unroll
        for (int nt = 0; nt < 8; nt++) {
            int col = e0 + wn * 64 + nt * 8 + (lane & 3) * 2;
            float cv0 = g_cvec[col];
            float cv1 = g_cvec[col + 1];
            int row0 = rowBase + wm * 64 + mt * 16 + (lane >> 2);
#pragma unroll
            for (int half = 0; half < 2; half++) {
                int row = row0 + half * 8;
                float2 o;
                o.x = tanhf(acc[mt][nt][half * 2 + 0] + cv0);
                o.y = tanhf(acc[mt][nt][half * 2 + 1] + cv1);
                *reinterpret_cast<float2*>(&out[(size_t)row * D_ + col]) = o;
            }
        }
    }
}

// ============================================================
// launch
// ============================================================
extern "C" void kernel_launch(void* const* d_in, const int* in_sizes, int n_in,
                              void* d_out, int out_size)
{
    const float* x  = (const float*)d_in[0];
    const float* Wr = (const float*)d_in[1];
    const float* br = (const float*)d_in[2];
    const float* Ww = (const float*)d_in[3];
    const float* bw = (const float*)d_in[4];
    const float* Wm = (const float*)d_in[5];
    const float* bm = (const float*)d_in[6];
    const float* Wp = (const float*)d_in[7];
    const float* bp = (const float*)d_in[8];
    const float* Wo = (const float*)d_in[9];
    const float* bo = (const float*)d_in[10];
    float* out = (float*)d_out;

    // 0) fused pack: X->fp16, Wo_x->g_wall, gate weights
    k0_pack<<<34176, 256>>>(x, Wo, Wr, Ww, Wm);

    // 1) gates GEMM (mma.sync fp16)
    k1_rwm<<<R_ / 128, 256>>>(br, bw, bm);

    // 2) folded weights (split-K, fused part + fused reduce/convert)
    k2_part<<<96, 256>>>(Wp, Wo, bp);
    k2_red<<<132, 256>>>(bo);

    // 3) linear-recurrence scan (emits fp16 Q into g_xq)
    k3a_chunk<<<(B_ * M_ * NC_) / 256, 256>>>();
    k3b_prefix<<<1, 256>>>();
    k3c_emit<<<(B_ * M_ * NC_) / 256, 256>>>();

    // 4) output GEMM + tanh (mma.sync fp16, R10-exact k4)
    dim3 grid4(D_ / 128, R_ / 128);
    k4_mm<<<grid4, 128>>>(out);
}

// round 14
// speedup vs baseline: 1.5114x; 1.0419x over previous
#include <cuda_runtime.h>
#include <cuda_fp16.h>
#include <math.h>

typedef unsigned int u32;

// Problem constants
#define B_   8
#define S_   4096
#define D_   1024
#define M_   32
#define R_   (B_*S_)      // 32768 rows
#define NC_  128
#define CHUNK_ 32
#define KP_  1056         // K for k4: [X(1024) | Q(32)]
#define NS4  33           // 1056 / 32 K-chunks

// -------- device scratch --------
__device__ float  g_r [R_*M_];
__device__ float  g_w [R_*M_];
__device__ float  g_nm[R_*M_];
__device__ float  g_wqp[8*M_*D_];         // split-K partials for Wq
__device__ float  g_cvec[D_];
__device__ float  g_cvp[8*D_];            // split-K partials for cvec
__device__ float  g_cA[B_*NC_*M_];
__device__ float  g_cB[B_*NC_*M_];
__device__ float  g_ms[B_*NC_*M_];
__device__ __half g_xq[(size_t)R_*KP_];   // fp16 [X | Q]
__device__ __half g_wall[(size_t)KP_*D_]; // fp16 [Wo_x ; Wq], K-major rows of N=1024
__device__ __half g_wg[D_*96];            // fp16 packed [Wr|Ww|Wm]

// ---------------- helpers ----------------
__device__ __forceinline__ void mma_f16(float* c, const u32* a, const u32* b) {
    asm volatile(
        "mma.sync.aligned.m16n8k16.row.col.f32.f16.f16.f32 "
        "{%0,%1,%2,%3},{%4,%5,%6,%7},{%8,%9},{%0,%1,%2,%3};\n"
        : "+f"(c[0]), "+f"(c[1]), "+f"(c[2]), "+f"(c[3])
        : "r"(a[0]), "r"(a[1]), "r"(a[2]), "r"(a[3]), "r"(b[0]), "r"(b[1]));
}
__device__ __forceinline__ void ldsm_x4(u32* r, u32 addr) {
    asm volatile("ldmatrix.sync.aligned.m8n8.x4.shared.b16 {%0,%1,%2,%3},[%4];"
        : "=r"(r[0]), "=r"(r[1]), "=r"(r[2]), "=r"(r[3]) : "r"(addr));
}
__device__ __forceinline__ void ldsm_x2t(u32* r, u32 addr) {
    asm volatile("ldmatrix.sync.aligned.m8n8.x2.trans.shared.b16 {%0,%1},[%2];"
        : "=r"(r[0]), "=r"(r[1]) : "r"(addr));
}
__device__ __forceinline__ void ldsm_x4t(u32* r, u32 addr) {
    asm volatile("ldmatrix.sync.aligned.m8n8.x4.trans.shared.b16 {%0,%1,%2,%3},[%4];"
        : "=r"(r[0]), "=r"(r[1]), "=r"(r[2]), "=r"(r[3]) : "r"(addr));
}
__device__ __forceinline__ void cpa16(u32 saddr, const void* gptr) {
    asm volatile("cp.async.cg.shared.global [%0], [%1], 16;" :: "r"(saddr), "l"(gptr));
}
__device__ __forceinline__ void cpa_commit() { asm volatile("cp.async.commit_group;"); }
__device__ __forceinline__ void cpa_wait1()  { asm volatile("cp.async.wait_group 1;"); }
__device__ __forceinline__ void cpa_wait0()  { asm volatile("cp.async.wait_group 0;"); }

// ============================================================
// K0: pack kernel (Wo_x -> g_wall fp16, gate weights -> g_wg)
// grid: [0,1024) Wo | [1024,1408) gates
// ============================================================
__global__ void __launch_bounds__(256) k0_pack(
    const float* __restrict__ Wo,
    const float* __restrict__ Wr, const float* __restrict__ Ww,
    const float* __restrict__ Wm)
{
    int bid = blockIdx.x;
    if (bid < 1024) {
        int i = bid * 256 + threadIdx.x;   // float4 over D_*D_
        float4 v = *reinterpret_cast<const float4*>(Wo + (size_t)i * 4);
        __half2 h0 = __floats2half2_rn(v.x, v.y);
        __half2 h1 = __floats2half2_rn(v.z, v.w);
        *reinterpret_cast<__half2*>(g_wall + (size_t)i * 4)     = h0;
        *reinterpret_cast<__half2*>(g_wall + (size_t)i * 4 + 2) = h1;
    } else {
        int i = (bid - 1024) * 256 + threadIdx.x;   // over D_*96
        int row = i / 96;
        int n = i % 96;
        float v;
        if (n < 32)      v = Wr[row * M_ + n];
        else if (n < 64) v = Ww[row * M_ + (n - 32)];
        else             v = Wm[row * M_ + (n - 64)];
        g_wg[i] = __float2half_rn(v);
    }
}

// ============================================================
// K1: gates GEMM (32768 x 96) = X @ [Wr|Ww|Wm], mma.sync fp16
// A path: f32 LDG -> convert -> STS (also STG fp16 X to g_xq)
// B path: cp.async from g_wg (pre-converted)
// ============================================================
#define APADH   40
#define A_BYT   10240
#define B1PADH  104
#define STG1    16896

__device__ __forceinline__ void k1_loadA(
    const float* __restrict__ x, int rowBase, int t, int k0, float4* ar)
{
#pragma unroll
    for (int u = 0; u < 2; u++) {
        int idx = t + u * 256;
        int row = idx >> 2;
        int c = idx & 3;
        const float* src = x + (size_t)(rowBase + row) * D_ + k0 + c * 8;
        ar[u * 2]     = *reinterpret_cast<const float4*>(src);
        ar[u * 2 + 1] = *reinterpret_cast<const float4*>(src + 4);
    }
}

__device__ __forceinline__ void k1_storeA(
    char* sbase, int rowBase, int t, int k0, const float4* ar)
{
#pragma unroll
    for (int u = 0; u < 2; u++) {
        int idx = t + u * 256;
        int row = idx >> 2;
        int c = idx & 3;
        __half2 h0 = __floats2half2_rn(ar[u*2].x,   ar[u*2].y);
        __half2 h1 = __floats2half2_rn(ar[u*2].z,   ar[u*2].w);
        __half2 h2 = __floats2half2_rn(ar[u*2+1].x, ar[u*2+1].y);
        __half2 h3 = __floats2half2_rn(ar[u*2+1].z, ar[u*2+1].w);
        uint4 pk;
        pk.x = *reinterpret_cast<u32*>(&h0);
        pk.y = *reinterpret_cast<u32*>(&h1);
        pk.z = *reinterpret_cast<u32*>(&h2);
        pk.w = *reinterpret_cast<u32*>(&h3);
        *reinterpret_cast<uint4*>(sbase + row * 80 + c * 16) = pk;
        *reinterpret_cast<uint4*>(g_xq + (size_t)(rowBase + row) * KP_ + k0 + c * 8) = pk;
    }
}

__device__ __forceinline__ void k1_copyB(u32 sbase, int t, int k0)
{
#pragma unroll
    for (int u = 0; u < 2; u++) {
        int idx = t + u * 256;
        if (idx < 384) {
            int row = idx / 12;
            int c = idx % 12;
            const __half* g = g_wg + (size_t)(k0 + row) * 96 + c * 8;
            cpa16(sbase + A_BYT + row * 208 + c * 16, g);
        }
    }
}

__global__ void __launch_bounds__(256) k1_rwm(
    const float* __restrict__ x,
    const float* __restrict__ br, const float* __restrict__ bw,
    const float* __restrict__ bm)
{
    __shared__ __align__(16) char sm1[2 * STG1];
    const int t = threadIdx.x;
    const int rowBase = blockIdx.x * 128;
    const int wid = t >> 5;
    const int lane = t & 31;
    const int wm = wid >> 1;
    const int wn = wid & 1;
    const u32 smBase = (u32)__cvta_generic_to_shared(sm1);

    float acc[2][6][4];
#pragma unroll
    for (int i = 0; i < 2; i++) {
#pragma unroll
        for (int j = 0; j < 6; j++) {
#pragma unroll
            for (int kq = 0; kq < 4; kq++) acc[i][j][kq] = 0.f;
        }
    }

    const int NS = 32;
    float4 ar[4];
    // prologue: stage A0, A1 via registers; B0, B1 via cp.async
    k1_loadA(x, rowBase, t, 0, ar);
    k1_storeA(sm1, rowBase, t, 0, ar);
    k1_loadA(x, rowBase, t, 32, ar);
    k1_storeA(sm1 + STG1, rowBase, t, 32, ar);
    k1_copyB(smBase, t, 0);
    cpa_commit();
    k1_copyB(smBase + STG1, t, 32);
    cpa_commit();
    cpa_wait1();
    __syncthreads();

    for (int s = 0; s < NS; s++) {
        if (s + 2 < NS) k1_loadA(x, rowBase, t, (s + 2) * 32, ar);
        u32 buf = smBase + (u32)(s & 1) * STG1;
        char* bufp = sm1 + (s & 1) * STG1;
#pragma unroll
        for (int kh = 0; kh < 2; kh++) {
            int kk = kh * 16;
            u32 a[2][4];
#pragma unroll
            for (int mt = 0; mt < 2; mt++) {
                int r = wm * 32 + mt * 16 + (lane & 15);
                int kc = kk + ((lane >> 4) << 3);
                ldsm_x4(a[mt], buf + (r * APADH + kc) * 2);
            }
            int krow = kk + (lane & 7) + ((lane >> 3) & 1) * 8;
#pragma unroll
            for (int nt = 0; nt < 6; nt++) {
                int nn = wn * 48 + nt * 8;
                u32 b[2];
                ldsm_x2t(b, buf + A_BYT + (krow * B1PADH + nn) * 2);
#pragma unroll
                for (int mt = 0; mt < 2; mt++) {
                    mma_f16(acc[mt][nt], a[mt], b);
                }
            }
        }
        __syncthreads();
        if (s + 2 < NS) {
            k1_storeA(bufp, rowBase, t, (s + 2) * 32, ar);
            k1_copyB(buf, t, (s + 2) * 32);
            cpa_commit();
        }
        if (s + 1 < NS) {
            if (s + 2 < NS) cpa_wait1();
            else cpa_wait0();
            __syncthreads();
        }
    }

#pragma unroll
    for (int mt = 0; mt < 2; mt++) {
#pragma unroll
        for (int nt = 0; nt < 6; nt++) {
            int n = wn * 48 + nt * 8 + (lane & 3) * 2;
            int row0 = rowBase + wm * 32 + mt * 16 + (lane >> 2);
#pragma unroll
            for (int half = 0; half < 2; half++) {
                int row = row0 + half * 8;
                float v0 = acc[mt][nt][half * 2 + 0];
                float v1 = acc[mt][nt][half * 2 + 1];
                float2 o;
                if (n < 32) {
                    o.x = 1.f / (1.f + expf(-(v0 + br[n])));
                    o.y = 1.f / (1.f + expf(-(v1 + br[n + 1])));
                    *reinterpret_cast<float2*>(&g_r[(size_t)row * M_ + n]) = o;
                } else if (n < 64) {
                    o.x = 1.f / (1.f + expf(-(v0 + bw[n - 32])));
                    o.y = 1.f / (1.f + expf(-(v1 + bw[n - 31])));
                    *reinterpret_cast<float2*>(&g_w[(size_t)row * M_ + n - 32]) = o;
                } else {
                    o.x = v0 + bm[n - 64];
                    o.y = v1 + bm[n - 63];
                    *reinterpret_cast<float2*>(&g_nm[(size_t)row * M_ + n - 64]) = o;
                }
            }
        }
    }
}

// ============================================================
// K2: Wq = Wp @ Wo_m and cvec = bp @ Wo_m + bo, split-K x8
// ============================================================
__global__ void __launch_bounds__(256) k2_part(
    const float* __restrict__ Wp, const float* __restrict__ Wo,
    const float* __restrict__ bp)
{
    __shared__ float Ps[32][128];
    const int t = threadIdx.x;
    int bid = blockIdx.x;
    if (bid < 64) {
        int eb = bid & 7;
        int ks = bid >> 3;
        const int e = eb * 128 + (t & 127);
        const int d0 = ks * 128;
        const int mg = t >> 7;
        float acc[16];
#pragma unroll
        for (int i = 0; i < 16; i++) acc[i] = 0.f;
#pragma unroll
        for (int u = 0; u < 16; u++) {
            int idx = t + u * 256;
            Ps[idx >> 7][idx & 127] = Wp[(idx >> 7) * D_ + d0 + (idx & 127)];
        }
        __syncthreads();
#pragma unroll 4
        for (int dd = 0; dd < 128; dd++) {
            float wo = Wo[(size_t)(D_ + d0 + dd) * D_ + e];
#pragma unroll
            for (int i = 0; i < 16; i++)
                acc[i] += Ps[mg * 16 + i][dd] * wo;
        }
#pragma unroll
        for (int i = 0; i < 16; i++)
            g_wqp[((size_t)ks * M_ + mg * 16 + i) * D_ + e] = acc[i];
    } else {
        int b2 = bid - 64;
        int eb = b2 & 3;
        int ks = b2 >> 2;
        int e = eb * 256 + t;
        int d0 = ks * 128;
        float acc = 0.f;
#pragma unroll 4
        for (int dd = 0; dd < 128; dd++)
            acc += bp[d0 + dd] * Wo[(size_t)(D_ + d0 + dd) * D_ + e];
        g_cvp[ks * D_ + e] = acc;
    }
}

__global__ void __launch_bounds__(256) k2_red(const float* __restrict__ bo)
{
    int bid = blockIdx.x;
    if (bid < 128) {
        int i = bid * 256 + threadIdx.x;   // over M_*D_
        float s = 0.f;
#pragma unroll
        for (int ks = 0; ks < 8; ks++)
            s += g_wqp[ks * M_ * D_ + i];
        g_wall[(size_t)1024 * D_ + i] = __float2half_rn(s);
    } else {
        int e = (bid - 128) * 256 + threadIdx.x;
        float s = bo[e];
#pragma unroll
        for (int ks = 0; ks < 8; ks++)
            s += g_cvp[ks * D_ + e];
        g_cvec[e] = s;
    }
}

// ============================================================
// K3: chunked parallel scan of mem[t+1] = (1-w)*mem + w*nm
// NC_=128 chunks of CHUNK_=32 steps
// ============================================================
__global__ void __launch_bounds__(256) k3a_chunk()
{
    int g = blockIdx.x * 256 + threadIdx.x;   // 32768 threads
    int m = g & 31;
    int c = (g >> 5) & (NC_ - 1);
    int b = g >> 12;
    size_t base = ((size_t)b * S_ + (size_t)c * CHUNK_) * M_ + m;
    float A = 1.f;
    float Bc = 0.f;
    for (int i = 0; i < CHUNK_; i++) {
        size_t idx = base + (size_t)i * M_;
        float wv = g_w[idx];
        float a = 1.f - wv;
        A = a * A;
        Bc = a * Bc + wv * g_nm[idx];
    }
    g_cA[g] = A;
    g_cB[g] = Bc;
}

__global__ void k3b_prefix()
{
    int t = threadIdx.x;
    int b = t >> 5;
    int m = t & 31;
    float mem = 0.f;
    for (int g0 = 0; g0 < NC_; g0 += 16) {
        float av[16];
        float bv[16];
#pragma unroll
        for (int j = 0; j < 16; j++) {
            int gi = (b * NC_ + g0 + j) * 32 + m;
            av[j] = g_cA[gi];
            bv[j] = g_cB[gi];
        }
#pragma unroll
        for (int j = 0; j < 16; j++) {
            int gi = (b * NC_ + g0 + j) * 32 + m;
            g_ms[gi] = mem;
            mem = av[j] * mem + bv[j];
        }
    }
}

__global__ void __launch_bounds__(256) k3c_emit()
{
    int g = blockIdx.x * 256 + threadIdx.x;
    int m = g & 31;
    int c = (g >> 5) & (NC_ - 1);
    int b = g >> 12;
    int row0 = b * S_ + c * CHUNK_;
    float mem = g_ms[g];
    for (int i = 0; i < CHUNK_; i++) {
        int row = row0 + i;
        size_t idx = (size_t)row * M_ + m;
        float rv = g_r[idx];
        float wv = g_w[idx];
        float nv = g_nm[idx];
        g_xq[(size_t)row * KP_ + 1024 + m] = __float2half_rn(rv * mem);
        mem = (1.f - wv) * mem + wv * nv;
    }
}

// ============================================================
// K4: out(32768,1024) = tanh( g_xq @ g_wall + cvec ), K=1056
// CTA 128x128, 128 threads (4 warps, 2m x 2n), warp tile 64x64
// R10-exact: static smem, 2-stage, copy AFTER MMA, two barriers
// ============================================================
#define B4PADH  136
#define B4_BYT  8704
#define STG4    18944      // A_BYT + B4_BYT

__device__ __forceinline__ void k4_copy(u32 sbase, int rowBase, int e0, int t, int k0)
{
#pragma unroll
    for (int u = 0; u < 4; u++) {
        int idx = t + u * 128;
        int row = idx >> 2;
        int c = idx & 3;
        cpa16(sbase + row * 80 + c * 16,
              g_xq + (size_t)(rowBase + row) * KP_ + k0 + c * 8);
    }
#pragma unroll
    for (int u = 0; u < 4; u++) {
        int idx = t + u * 128;
        int row = idx >> 4;
        int c = idx & 15;
        cpa16(sbase + A_BYT + row * 272 + c * 16,
              g_wall + (size_t)(k0 + row) * D_ + e0 + c * 8);
    }
}

__global__ void __launch_bounds__(128) k4_mm(float* __restrict__ out)
{
    __shared__ __align__(16) char sm4[2 * STG4];
    const int t = threadIdx.x;
    const int rowBase = blockIdx.y * 128;
    const int e0 = blockIdx.x * 128;
    const int wid = t >> 5;
    const int lane = t & 31;
    const int wm = wid >> 1;     // 0..1 -> rows wm*64
    const int wn = wid & 1;      // 0..1 -> cols wn*64
    const u32 smBase = (u32)__cvta_generic_to_shared(sm4);

    float acc[4][8][4];
#pragma unroll
    for (int i = 0; i < 4; i++) {
#pragma unroll
        for (int j = 0; j < 8; j++) {
#pragma unroll
            for (int kq = 0; kq < 4; kq++) acc[i][j][kq] = 0.f;
        }
    }

    k4_copy(smBase, rowBase, e0, t, 0);
    cpa_commit();
    k4_copy(smBase + STG4, rowBase, e0, t, 32);
    cpa_commit();
    cpa_wait1();
    __syncthreads();

    for (int s = 0; s < NS4; s++) {
        u32 buf = smBase + (u32)(s & 1) * STG4;
#pragma unroll
        for (int kh = 0; kh < 2; kh++) {
            int kk = kh * 16;
            u32 a[4][4];
#pragma unroll
            for (int mt = 0; mt < 4; mt++) {
                int r = wm * 64 + mt * 16 + (lane & 15);
                int kc = kk + ((lane >> 4) << 3);
                ldsm_x4(a[mt], buf + (r * APADH + kc) * 2);
            }
            int krow = kk + (lane & 7) + ((lane >> 3) & 1) * 8;
            int ncol = ((lane >> 4) << 3);
#pragma unroll
            for (int nt4 = 0; nt4 < 4; nt4++) {
                int nn = wn * 64 + nt4 * 16;
                u32 b[4];
                ldsm_x4t(b, buf + A_BYT + (krow * B4PADH + nn + ncol) * 2);
#pragma unroll
                for (int mt = 0; mt < 4; mt++) {
                    mma_f16(acc[mt][2 * nt4],     a[mt], b);
                    mma_f16(acc[mt][2 * nt4 + 1], a[mt], b + 2);
                }
            }
        }
        __syncthreads();
        if (s + 2 < NS4) {
            k4_copy(buf, rowBase, e0, t, (s + 2) * 32);
            cpa_commit();
        }
        if (s + 1 < NS4) {
            if (s + 2 < NS4) cpa_wait1();
            else cpa_wait0();
            __syncthreads();
        }
    }

    // epilogue: + cvec, tanh
#pragma unroll
    for (int mt = 0; mt < 4; mt++) {
#pragma unroll
        for (int nt = 0; nt < 8; nt++) {
            int col = e0 + wn * 64 + nt * 8 + (lane & 3) * 2;
            float cv0 = g_cvec[col];
            float cv1 = g_cvec[col + 1];
            int row0 = rowBase + wm * 64 + mt * 16 + (lane >> 2);
#pragma unroll
            for (int half = 0; half < 2; half++) {
                int row = row0 + half * 8;
                float2 o;
                o.x = tanhf(acc[mt][nt][half * 2 + 0] + cv0);
                o.y = tanhf(acc[mt][nt][half * 2 + 1] + cv1);
                *reinterpret_cast<float2*>(&out[(size_t)row * D_ + col]) = o;
            }
        }
    }
}

// ============================================================
// launch
// ============================================================
extern "C" void kernel_launch(void* const* d_in, const int* in_sizes, int n_in,
                              void* d_out, int out_size)
{
    const float* x  = (const float*)d_in[0];
    const float* Wr = (const float*)d_in[1];
    const float* br = (const float*)d_in[2];
    const float* Ww = (const float*)d_in[3];
    const float* bw = (const float*)d_in[4];
    const float* Wm = (const float*)d_in[5];
    const float* bm = (const float*)d_in[6];
    const float* Wp = (const float*)d_in[7];
    const float* bp = (const float*)d_in[8];
    const float* Wo = (const float*)d_in[9];
    const float* bo = (const float*)d_in[10];
    float* out = (float*)d_out;

    // 0) pack Wo_x + gate weights to fp16 (X conversion is fused into k1)
    k0_pack<<<1408, 256>>>(Wo, Wr, Ww, Wm);

    // 1) gates GEMM (mma.sync fp16); converts X->fp16 into g_xq on the fly
    k1_rwm<<<R_ / 128, 256>>>(x, br, bw, bm);

    // 2) folded weights (split-K, fused part + fused reduce/convert)
    k2_part<<<96, 256>>>(Wp, Wo, bp);
    k2_red<<<132, 256>>>(bo);

    // 3) linear-recurrence scan (emits fp16 Q into g_xq)
    k3a_chunk<<<(B_ * M_ * NC_) / 256, 256>>>();
    k3b_prefix<<<1, 256>>>();
    k3c_emit<<<(B_ * M_ * NC_) / 256, 256>>>();

    // 4) output GEMM + tanh (mma.sync fp16, R10-exact k4)
    dim3 grid4(D_ / 128, R_ / 128);
    k4_mm<<<grid4, 128>>>(out);
}